// round 8
// baseline (speedup 1.0000x reference)
#include <cuda_runtime.h>
#include <cuda.h>
#include <cstdint>

// CapsuleLayer dynamic routing — persistent CTAs, flat TMA stream, depth-3.
// x: [B=256, N=1152, CI=8] f32, w: [C=10, N=1152, CI=8, CO=16] f32
// out: [C, B, 1, 1, 16] f32
//
// Grid = 128 persistent CTAs, one per b-pair; each sweeps c = 0..9.
// w is one contiguous 2D stream (128 floats x 11520 rows, SW128 boxes of
// 32 floats x 144 rows): 80 blocks total, triple-buffered TMA with
// mbarrier+expect_tx; block q+3 is always in flight. Every 8 blocks the
// register-resident priors P[8][8] run the 3 routing iterations (phase 2),
// overlapped with the next tile's fetches.

#define Cc 10
#define Bb 256
#define Nn 1152
#define NTHREADS 576
#define NWARPS 18
#define RPB 144
#define NBUF 3
#define QTOT 80                  // 10 tiles x 8 blocks
#define COLW  18432              // bytes per 128B-column box (144*128)
#define BUFB  (4*COLW)           // 73728 bytes per buffer
#define MBAR_OFF (NBUF*BUFB)     // 221184
#define WRED_OFF (MBAR_OFF + 64)
#define SRED_OFF (WRED_OFF + NWARPS*2*16*4)
#define OUTV_OFF (SRED_OFF + NWARPS*2*4)
#define SMEM_BYTES (OUTV_OFF + 2*16*4)

__device__ __forceinline__ void mbar_init(uint32_t a, uint32_t cnt) {
    asm volatile("mbarrier.init.shared.b64 [%0], %1;" :: "r"(a), "r"(cnt) : "memory");
}
__device__ __forceinline__ void mbar_expect_tx(uint32_t a, uint32_t bytes) {
    asm volatile("mbarrier.arrive.expect_tx.shared.b64 _, [%0], %1;"
                 :: "r"(a), "r"(bytes) : "memory");
}
__device__ __forceinline__ void mbar_wait(uint32_t a, uint32_t parity) {
    asm volatile(
        "{\n\t.reg .pred P1;\n\t"
        "W_%=:\n\t"
        "mbarrier.try_wait.parity.acquire.cta.shared::cta.b64 P1, [%0], %1, 0x989680;\n\t"
        "@P1 bra.uni D_%=;\n\t"
        "bra.uni W_%=;\n\t"
        "D_%=:\n\t}"
        :: "r"(a), "r"(parity) : "memory");
}
__device__ __forceinline__ void tma2d(uint32_t dst, const CUtensorMap* m,
                                      int cx, int cy, uint32_t mb) {
    asm volatile(
        "cp.async.bulk.tensor.2d.shared::cta.global.tile.mbarrier::complete_tx::bytes "
        "[%0], [%1, {%2, %3}], [%4];"
        :: "r"(dst), "l"(m), "r"(cx), "r"(cy), "r"(mb) : "memory");
}

__global__ __launch_bounds__(NTHREADS, 1)
void capsule_kernel(const __grid_constant__ CUtensorMap tmap,
                    const float* __restrict__ x,
                    float* __restrict__ out)
{
    extern __shared__ char smc[];
    float* wred = (float*)(smc + WRED_OFF);    // [18][2][16]
    float* sred = (float*)(smc + SRED_OFF);    // [18][2]
    float* outv = (float*)(smc + OUTV_OFF);    // [2][16]

    const int tid  = threadIdx.x;
    const int g    = tid & 1;               // which b of pair
    const int oh   = (tid >> 1) & 1;        // which CO half
    const int rw   = tid >> 2;              // row within block, 0..143
    const int lane = tid & 31;
    const int wid  = tid >> 5;
    const int bbase = blockIdx.x << 1;      // pair base
    const int b    = bbase + g;

    const uint32_t sbase = (uint32_t)__cvta_generic_to_shared(smc);
    const uint32_t mb0 = sbase + MBAR_OFF;

    auto stage = [&](int q) {               // tid 0 only
        const uint32_t dstb = sbase + (uint32_t)((q % NBUF) * BUFB);
        const int cy = q * RPB;
        mbar_expect_tx(mb0 + (q % NBUF) * 8, BUFB);
        #pragma unroll
        for (int j = 0; j < 4; ++j)
            tma2d(dstb + j * COLW, &tmap, j * 32, cy, mb0 + (q % NBUF) * 8);
    };

    if (tid == 0) {
        mbar_init(mb0 + 0, 1);
        mbar_init(mb0 + 8, 1);
        mbar_init(mb0 + 16, 1);
    }
    __syncthreads();
    if (tid == 0) { stage(0); stage(1); stage(2); }

    float P[8][8];
    const int r7  = rw & 7;
    const int oh2 = oh * 2;
    const uint32_t rowoff = (uint32_t)rw * 128;

    for (int t = 0; t < Cc; ++t) {
        // ======== Phase 1: 8 blocks of this tile -> P[8][8] ========
        #pragma unroll
        for (int s = 0; s < 8; ++s) {
            const int q  = t * 8 + s;
            const int bi = q % NBUF;
            mbar_wait(mb0 + bi * 8, (q / NBUF) & 1);

            const int n = s * RPB + rw;
            const float* xp = x + ((size_t)b * Nn + n) * 8;
            const float4 xa = *(const float4*)xp;
            const float4 xb = *(const float4*)(xp + 4);
            const float xv[8] = {xa.x, xa.y, xa.z, xa.w, xb.x, xb.y, xb.z, xb.w};

            #pragma unroll
            for (int o = 0; o < 8; ++o) P[s][o] = 0.f;

            const char* bufp = smc + (size_t)bi * BUFB + rowoff;
            #pragma unroll
            for (int i = 0; i < 8; ++i) {
                const float xvi = xv[i];
                #pragma unroll
                for (int m = 0; m < 2; ++m) {
                    const int C = i * 4 + m;                 // 16B unit (oh=0 base)
                    const uint32_t u = (uint32_t)((C & 7) + oh2);
                    const uint32_t off = (uint32_t)((C >> 3) * COLW)
                                       + ((u ^ (uint32_t)r7) << 4);
                    const float4 wv = *(const float4*)(bufp + off);
                    P[s][m*4+0] = fmaf(xvi, wv.x, P[s][m*4+0]);
                    P[s][m*4+1] = fmaf(xvi, wv.y, P[s][m*4+1]);
                    P[s][m*4+2] = fmaf(xvi, wv.z, P[s][m*4+2]);
                    P[s][m*4+3] = fmaf(xvi, wv.w, P[s][m*4+3]);
                }
            }

            __syncthreads();                 // all done reading buffer bi
            if (tid == 0 && q + NBUF < QTOT) stage(q + NBUF);
        }

        // ======== Phase 2: routing for tile c = t ========
        float Lr[8];

        // ---- iteration 0: s = mean_n priors ----
        {
            float acc[8];
            #pragma unroll
            for (int o = 0; o < 8; ++o) {
                float a = 0.f;
                #pragma unroll
                for (int k = 0; k < 8; ++k) a += P[k][o];
                acc[o] = a;
            }
            #pragma unroll
            for (int off = 4; off <= 16; off <<= 1)
                #pragma unroll
                for (int o = 0; o < 8; ++o)
                    acc[o] += __shfl_xor_sync(0xffffffffu, acc[o], off);
            if (lane < 4) {
                #pragma unroll
                for (int o = 0; o < 8; ++o)
                    wred[(wid * 2 + g) * 16 + oh * 8 + o] = acc[o];
            }
            __syncthreads();
            if (tid < 32) {
                const int g2 = tid & 1, o2 = tid >> 1;
                float sv = 0.f;
                #pragma unroll
                for (int wi = 0; wi < NWARPS; ++wi)
                    sv += wred[(wi * 2 + g2) * 16 + o2];
                sv *= (1.0f / Nn);
                float sq = sv * sv;
                #pragma unroll
                for (int off = 2; off <= 16; off <<= 1)
                    sq += __shfl_xor_sync(0xffffffffu, sq, off);
                const float coef = sq / (1.f + sq) * rsqrtf(sq);
                outv[g2 * 16 + o2] = sv * coef;
            }
            __syncthreads();
        }

        // ---- iterations 1 and 2 ----
        #pragma unroll
        for (int it = 1; it < 3; ++it) {
            float ovr[8];
            #pragma unroll
            for (int o = 0; o < 8; ++o) ovr[o] = outv[g * 16 + oh * 8 + o];

            float lmax = -1e30f;
            #pragma unroll
            for (int k = 0; k < 8; ++k) {
                float dot = 0.f;
                #pragma unroll
                for (int o = 0; o < 8; ++o) dot = fmaf(P[k][o], ovr[o], dot);
                dot += __shfl_xor_sync(0xffffffffu, dot, 2);   // join o-halves
                const float L = (it == 1) ? dot : (Lr[k] + dot);
                Lr[k] = L;
                lmax = fmaxf(lmax, L);
            }
            #pragma unroll
            for (int off = 4; off <= 16; off <<= 1)
                lmax = fmaxf(lmax, __shfl_xor_sync(0xffffffffu, lmax, off));
            __syncthreads();                 // previous sred consumers done
            if (lane < 2) sred[wid * 2 + g] = lmax;
            __syncthreads();
            float M = -1e30f;
            #pragma unroll
            for (int wi = 0; wi < NWARPS; ++wi)
                M = fmaxf(M, sred[wi * 2 + g]);

            float e[8], lsum = 0.f;
            #pragma unroll
            for (int k = 0; k < 8; ++k) {
                e[k] = __expf(Lr[k] - M);
                lsum += e[k];
            }
            #pragma unroll
            for (int off = 4; off <= 16; off <<= 1)
                lsum += __shfl_xor_sync(0xffffffffu, lsum, off);
            __syncthreads();                 // all M reads done
            if (lane < 2) sred[wid * 2 + g] = lsum;
            __syncthreads();
            float Z = 0.f;
            #pragma unroll
            for (int wi = 0; wi < NWARPS; ++wi)
                Z += sred[wi * 2 + g];

            float acc[8];
            #pragma unroll
            for (int o = 0; o < 8; ++o) {
                float a = 0.f;
                #pragma unroll
                for (int k = 0; k < 8; ++k) a = fmaf(e[k], P[k][o], a);
                acc[o] = a;
            }
            #pragma unroll
            for (int off = 4; off <= 16; off <<= 1)
                #pragma unroll
                for (int o = 0; o < 8; ++o)
                    acc[o] += __shfl_xor_sync(0xffffffffu, acc[o], off);
            if (lane < 4) {
                #pragma unroll
                for (int o = 0; o < 8; ++o)
                    wred[(wid * 2 + g) * 16 + oh * 8 + o] = acc[o];
            }
            __syncthreads();
            if (tid < 32) {
                const int g2 = tid & 1, o2 = tid >> 1;
                float sv = 0.f;
                #pragma unroll
                for (int wi = 0; wi < NWARPS; ++wi)
                    sv += wred[(wi * 2 + g2) * 16 + o2];
                sv /= Z;
                float sq = sv * sv;
                #pragma unroll
                for (int off = 2; off <= 16; off <<= 1)
                    sq += __shfl_xor_sync(0xffffffffu, sq, off);
                const float coef = sq / (1.f + sq) * rsqrtf(sq);
                outv[g2 * 16 + o2] = sv * coef;
            }
            __syncthreads();
        }

        // ======== output for tile t: [C, B, 1, 1, 16] ========
        if (tid < 32) {
            const int g2 = tid & 1, o2 = tid >> 1;
            out[((size_t)t * Bb + bbase + g2) * 16 + o2] = outv[g2 * 16 + o2];
        }
        __syncthreads();                     // outv stable before next tile
    }
}

// ---------------- host ----------------
typedef CUresult (*EncodeTiledFn)(
    CUtensorMap*, CUtensorMapDataType, cuuint32_t, void*,
    const cuuint64_t*, const cuuint64_t*, const cuuint32_t*, const cuuint32_t*,
    CUtensorMapInterleave, CUtensorMapSwizzle, CUtensorMapL2promotion,
    CUtensorMapFloatOOBfill);

extern "C" void kernel_launch(void* const* d_in, const int* in_sizes, int n_in,
                              void* d_out, int out_size)
{
    const float* x = (const float*)d_in[0];
    void* w = (void*)d_in[1];
    float* out = (float*)d_out;

    EncodeTiledFn encode = nullptr;
    cudaDriverEntryPointQueryResult qr;
    cudaGetDriverEntryPoint("cuTensorMapEncodeTiled", (void**)&encode,
                            cudaEnableDefault, &qr);

    CUtensorMap tmap;
    cuuint64_t dims[2]    = { 128, (cuuint64_t)Cc * Nn };
    cuuint64_t strides[1] = { 128 * 4 };
    cuuint32_t box[2]     = { 32, RPB };
    cuuint32_t estr[2]    = { 1, 1 };
    encode(&tmap, CU_TENSOR_MAP_DATA_TYPE_FLOAT32, 2, w,
           dims, strides, box, estr,
           CU_TENSOR_MAP_INTERLEAVE_NONE, CU_TENSOR_MAP_SWIZZLE_128B,
           CU_TENSOR_MAP_L2_PROMOTION_L2_128B,
           CU_TENSOR_MAP_FLOAT_OOB_FILL_NONE);

    cudaFuncSetAttribute(capsule_kernel,
                         cudaFuncAttributeMaxDynamicSharedMemorySize, SMEM_BYTES);

    const int grid = Bb / 2;   // 128 persistent CTAs
    capsule_kernel<<<grid, NTHREADS, SMEM_BYTES>>>(tmap, x, out);
}

// round 9
// speedup vs baseline: 1.1131x; 1.1131x over previous
#include <cuda_runtime.h>
#include <cuda.h>
#include <cstdint>

// CapsuleLayer dynamic routing — persistent CTAs (grid=148), flat TMA
// stream, depth-3 pipeline.
// x: [B=256, N=1152, CI=8] f32, w: [C=10, N=1152, CI=8, CO=16] f32
// out: [C, B, 1, 1, 16] f32
//
// Work = 1280 units (c, b-pair); CTA j handles units j, j+148, ...
// Unit u: c = u%10, pair = u/10. Each unit streams w[c] as 8 blocks of
// 144 rows (SW128 TMA boxes 32 floats x 144 rows) through 3 ping-pong
// buffers; block q+3 is always in flight, including across unit
// boundaries, so routing (phase 2) overlaps the next unit's fetches.
// Priors P[8][8] stay register-resident per unit.

#define Cc 10
#define Bb 256
#define Nn 1152
#define NTHREADS 576
#define NWARPS 18
#define RPB 144
#define NBUF 3
#define NUNITS_TOTAL 1280
#define GRID 148
#define COLW  18432              // bytes per 128B-column box (144*128)
#define BUFB  (4*COLW)           // 73728 bytes per buffer
#define MBAR_OFF (NBUF*BUFB)     // 221184
#define WRED_OFF (MBAR_OFF + 64)
#define SRED_OFF (WRED_OFF + NWARPS*2*16*4)
#define OUTV_OFF (SRED_OFF + NWARPS*2*4)
#define SMEM_BYTES (OUTV_OFF + 2*16*4)

__device__ __forceinline__ void mbar_init(uint32_t a, uint32_t cnt) {
    asm volatile("mbarrier.init.shared.b64 [%0], %1;" :: "r"(a), "r"(cnt) : "memory");
}
__device__ __forceinline__ void mbar_expect_tx(uint32_t a, uint32_t bytes) {
    asm volatile("mbarrier.arrive.expect_tx.shared.b64 _, [%0], %1;"
                 :: "r"(a), "r"(bytes) : "memory");
}
__device__ __forceinline__ void mbar_wait(uint32_t a, uint32_t parity) {
    asm volatile(
        "{\n\t.reg .pred P1;\n\t"
        "W_%=:\n\t"
        "mbarrier.try_wait.parity.acquire.cta.shared::cta.b64 P1, [%0], %1, 0x989680;\n\t"
        "@P1 bra.uni D_%=;\n\t"
        "bra.uni W_%=;\n\t"
        "D_%=:\n\t}"
        :: "r"(a), "r"(parity) : "memory");
}
__device__ __forceinline__ void tma2d(uint32_t dst, const CUtensorMap* m,
                                      int cx, int cy, uint32_t mb) {
    asm volatile(
        "cp.async.bulk.tensor.2d.shared::cta.global.tile.mbarrier::complete_tx::bytes "
        "[%0], [%1, {%2, %3}], [%4];"
        :: "r"(dst), "l"(m), "r"(cx), "r"(cy), "r"(mb) : "memory");
}

__global__ __launch_bounds__(NTHREADS, 1)
void capsule_kernel(const __grid_constant__ CUtensorMap tmap,
                    const float* __restrict__ x,
                    float* __restrict__ out)
{
    extern __shared__ char smc[];
    float* wred = (float*)(smc + WRED_OFF);    // [18][2][16]
    float* sred = (float*)(smc + SRED_OFF);    // [18][2]
    float* outv = (float*)(smc + OUTV_OFF);    // [2][16]

    const int tid  = threadIdx.x;
    const int g    = tid & 1;               // which b of pair
    const int oh   = (tid >> 1) & 1;        // which CO half
    const int rw   = tid >> 2;              // row within block, 0..143
    const int lane = tid & 31;
    const int wid  = tid >> 5;
    const int bid  = blockIdx.x;

    // units this CTA owns: u = bid + i*GRID, i in [0, nunits)
    const int nunits = (NUNITS_TOTAL - bid + GRID - 1) / GRID;
    const int qtot   = nunits * 8;

    const uint32_t sbase = (uint32_t)__cvta_generic_to_shared(smc);
    const uint32_t mb0 = sbase + MBAR_OFF;

    auto stage = [&](int q) {               // tid 0 only
        const int i = q >> 3, s = q & 7;
        const int u = bid + i * GRID;
        const int cy = (u % Cc) * Nn + s * RPB;
        const int bi = q % NBUF;
        const uint32_t dstb = sbase + (uint32_t)(bi * BUFB);
        mbar_expect_tx(mb0 + bi * 8, BUFB);
        #pragma unroll
        for (int j = 0; j < 4; ++j)
            tma2d(dstb + j * COLW, &tmap, j * 32, cy, mb0 + bi * 8);
    };

    if (tid == 0) {
        mbar_init(mb0 + 0, 1);
        mbar_init(mb0 + 8, 1);
        mbar_init(mb0 + 16, 1);
    }
    __syncthreads();
    if (tid == 0) { stage(0); stage(1); stage(2); }

    float P[8][8];
    const int r7  = rw & 7;
    const int oh2 = oh * 2;
    const uint32_t rowoff = (uint32_t)rw * 128;

    for (int i = 0; i < nunits; ++i) {
        const int u = bid + i * GRID;
        const int c = u % Cc;
        const int bbase = (u / Cc) * 2;
        const int b = bbase + g;

        // ======== Phase 1: 8 blocks of this unit -> P[8][8] ========
        #pragma unroll
        for (int s = 0; s < 8; ++s) {
            const int q  = i * 8 + s;
            const int bi = q % NBUF;
            mbar_wait(mb0 + bi * 8, (q / NBUF) & 1);

            const int n = s * RPB + rw;
            const float* xp = x + ((size_t)b * Nn + n) * 8;
            const float4 xa = *(const float4*)xp;
            const float4 xb = *(const float4*)(xp + 4);
            const float xv[8] = {xa.x, xa.y, xa.z, xa.w, xb.x, xb.y, xb.z, xb.w};

            #pragma unroll
            for (int o = 0; o < 8; ++o) P[s][o] = 0.f;

            const char* bufp = smc + (size_t)bi * BUFB + rowoff;
            #pragma unroll
            for (int ii = 0; ii < 8; ++ii) {
                const float xvi = xv[ii];
                #pragma unroll
                for (int m = 0; m < 2; ++m) {
                    const int C = ii * 4 + m;                // 16B unit (oh=0 base)
                    const uint32_t uu = (uint32_t)((C & 7) + oh2);
                    const uint32_t off = (uint32_t)((C >> 3) * COLW)
                                       + ((uu ^ (uint32_t)r7) << 4);
                    const float4 wv = *(const float4*)(bufp + off);
                    P[s][m*4+0] = fmaf(xvi, wv.x, P[s][m*4+0]);
                    P[s][m*4+1] = fmaf(xvi, wv.y, P[s][m*4+1]);
                    P[s][m*4+2] = fmaf(xvi, wv.z, P[s][m*4+2]);
                    P[s][m*4+3] = fmaf(xvi, wv.w, P[s][m*4+3]);
                }
            }

            __syncthreads();                 // all done reading buffer bi
            if (tid == 0 && q + NBUF < qtot) stage(q + NBUF);
        }

        // ======== Phase 2: routing for this unit ========
        float Lr[8];

        // ---- iteration 0: s = mean_n priors ----
        {
            float acc[8];
            #pragma unroll
            for (int o = 0; o < 8; ++o) {
                float a = 0.f;
                #pragma unroll
                for (int k = 0; k < 8; ++k) a += P[k][o];
                acc[o] = a;
            }
            #pragma unroll
            for (int off = 4; off <= 16; off <<= 1)
                #pragma unroll
                for (int o = 0; o < 8; ++o)
                    acc[o] += __shfl_xor_sync(0xffffffffu, acc[o], off);
            if (lane < 4) {
                #pragma unroll
                for (int o = 0; o < 8; ++o)
                    wred[(wid * 2 + g) * 16 + oh * 8 + o] = acc[o];
            }
            __syncthreads();
            if (tid < 32) {
                const int g2 = tid & 1, o2 = tid >> 1;
                float sv = 0.f;
                #pragma unroll
                for (int wi = 0; wi < NWARPS; ++wi)
                    sv += wred[(wi * 2 + g2) * 16 + o2];
                sv *= (1.0f / Nn);
                float sq = sv * sv;
                #pragma unroll
                for (int off = 2; off <= 16; off <<= 1)
                    sq += __shfl_xor_sync(0xffffffffu, sq, off);
                const float coef = sq / (1.f + sq) * rsqrtf(sq);
                outv[g2 * 16 + o2] = sv * coef;
            }
            __syncthreads();
        }

        // ---- iterations 1 and 2 ----
        #pragma unroll
        for (int it = 1; it < 3; ++it) {
            float ovr[8];
            #pragma unroll
            for (int o = 0; o < 8; ++o) ovr[o] = outv[g * 16 + oh * 8 + o];

            float lmax = -1e30f;
            #pragma unroll
            for (int k = 0; k < 8; ++k) {
                float dot = 0.f;
                #pragma unroll
                for (int o = 0; o < 8; ++o) dot = fmaf(P[k][o], ovr[o], dot);
                dot += __shfl_xor_sync(0xffffffffu, dot, 2);   // join o-halves
                const float L = (it == 1) ? dot : (Lr[k] + dot);
                Lr[k] = L;
                lmax = fmaxf(lmax, L);
            }
            #pragma unroll
            for (int off = 4; off <= 16; off <<= 1)
                lmax = fmaxf(lmax, __shfl_xor_sync(0xffffffffu, lmax, off));
            __syncthreads();                 // previous sred consumers done
            if (lane < 2) sred[wid * 2 + g] = lmax;
            __syncthreads();
            float M = -1e30f;
            #pragma unroll
            for (int wi = 0; wi < NWARPS; ++wi)
                M = fmaxf(M, sred[wi * 2 + g]);

            float e[8], lsum = 0.f;
            #pragma unroll
            for (int k = 0; k < 8; ++k) {
                e[k] = __expf(Lr[k] - M);
                lsum += e[k];
            }
            #pragma unroll
            for (int off = 4; off <= 16; off <<= 1)
                lsum += __shfl_xor_sync(0xffffffffu, lsum, off);
            __syncthreads();                 // all M reads done
            if (lane < 2) sred[wid * 2 + g] = lsum;
            __syncthreads();
            float Z = 0.f;
            #pragma unroll
            for (int wi = 0; wi < NWARPS; ++wi)
                Z += sred[wi * 2 + g];

            float acc[8];
            #pragma unroll
            for (int o = 0; o < 8; ++o) {
                float a = 0.f;
                #pragma unroll
                for (int k = 0; k < 8; ++k) a = fmaf(e[k], P[k][o], a);
                acc[o] = a;
            }
            #pragma unroll
            for (int off = 4; off <= 16; off <<= 1)
                #pragma unroll
                for (int o = 0; o < 8; ++o)
                    acc[o] += __shfl_xor_sync(0xffffffffu, acc[o], off);
            if (lane < 4) {
                #pragma unroll
                for (int o = 0; o < 8; ++o)
                    wred[(wid * 2 + g) * 16 + oh * 8 + o] = acc[o];
            }
            __syncthreads();
            if (tid < 32) {
                const int g2 = tid & 1, o2 = tid >> 1;
                float sv = 0.f;
                #pragma unroll
                for (int wi = 0; wi < NWARPS; ++wi)
                    sv += wred[(wi * 2 + g2) * 16 + o2];
                sv /= Z;
                float sq = sv * sv;
                #pragma unroll
                for (int off = 2; off <= 16; off <<= 1)
                    sq += __shfl_xor_sync(0xffffffffu, sq, off);
                const float coef = sq / (1.f + sq) * rsqrtf(sq);
                outv[g2 * 16 + o2] = sv * coef;
            }
            __syncthreads();
        }

        // ======== output for this unit: [C, B, 1, 1, 16] ========
        if (tid < 32) {
            const int g2 = tid & 1, o2 = tid >> 1;
            out[((size_t)c * Bb + bbase + g2) * 16 + o2] = outv[g2 * 16 + o2];
        }
        __syncthreads();                     // outv stable before next unit
    }
}

// ---------------- host ----------------
typedef CUresult (*EncodeTiledFn)(
    CUtensorMap*, CUtensorMapDataType, cuuint32_t, void*,
    const cuuint64_t*, const cuuint64_t*, const cuuint32_t*, const cuuint32_t*,
    CUtensorMapInterleave, CUtensorMapSwizzle, CUtensorMapL2promotion,
    CUtensorMapFloatOOBfill);

extern "C" void kernel_launch(void* const* d_in, const int* in_sizes, int n_in,
                              void* d_out, int out_size)
{
    const float* x = (const float*)d_in[0];
    void* w = (void*)d_in[1];
    float* out = (float*)d_out;

    EncodeTiledFn encode = nullptr;
    cudaDriverEntryPointQueryResult qr;
    cudaGetDriverEntryPoint("cuTensorMapEncodeTiled", (void**)&encode,
                            cudaEnableDefault, &qr);

    CUtensorMap tmap;
    cuuint64_t dims[2]    = { 128, (cuuint64_t)Cc * Nn };
    cuuint64_t strides[1] = { 128 * 4 };
    cuuint32_t box[2]     = { 32, RPB };
    cuuint32_t estr[2]    = { 1, 1 };
    encode(&tmap, CU_TENSOR_MAP_DATA_TYPE_FLOAT32, 2, w,
           dims, strides, box, estr,
           CU_TENSOR_MAP_INTERLEAVE_NONE, CU_TENSOR_MAP_SWIZZLE_128B,
           CU_TENSOR_MAP_L2_PROMOTION_L2_128B,
           CU_TENSOR_MAP_FLOAT_OOB_FILL_NONE);

    cudaFuncSetAttribute(capsule_kernel,
                         cudaFuncAttributeMaxDynamicSharedMemorySize, SMEM_BYTES);

    capsule_kernel<<<GRID, NTHREADS, SMEM_BYTES>>>(tmap, x, out);
}